// round 1
// baseline (speedup 1.0000x reference)
#include <cuda_runtime.h>
#include <cstdint>

typedef unsigned long long ull;

#define B_     16
#define D_     4096
#define NKV    8
#define HD     128
#define SEQ    4096
#define KSPLIT 16
#define KSLICE 256

// ---------------- scratch (no allocations allowed) ----------------
__device__ float g_q   [B_ * D_];            // l2-normed q   [b][h*128+d]
__device__ float g_kn  [B_ * NKV * HD];      // l2-normed new k
__device__ float g_vn  [B_ * NKV * HD];      // new v
__device__ float g_attn[B_ * D_];            // attention output
__device__ float g_Pq  [KSPLIT * B_ * D_];        // GEMM partials
__device__ float g_Pk  [KSPLIT * B_ * NKV * HD];
__device__ float g_Pv  [KSPLIT * B_ * NKV * HD];
__device__ float g_Po  [KSPLIT * B_ * D_];

// ---------------- packed f32x2 helpers ----------------
__device__ __forceinline__ ull ffma2(ull a, ull b, ull c) {
    ull d; asm("fma.rn.f32x2 %0,%1,%2,%3;" : "=l"(d) : "l"(a), "l"(b), "l"(c)); return d;
}
__device__ __forceinline__ ull fmul2(ull a, ull b) {
    ull d; asm("mul.rn.f32x2 %0,%1,%2;" : "=l"(d) : "l"(a), "l"(b)); return d;
}
__device__ __forceinline__ ull pack2(float x, float y) {
    ull d; asm("mov.b64 %0,{%1,%2};" : "=l"(d) : "f"(x), "f"(y)); return d;
}
__device__ __forceinline__ float2 unpack2(ull a) {
    float2 r; asm("mov.b64 {%0,%1},%2;" : "=f"(r.x), "=f"(r.y) : "l"(a)); return r;
}

// ---------------- skinny GEMM: out[16,N] = X[16,4096] @ W[4096,N] ----------------
// K split across grid.y (16 slices of 256), partials to scratch.
// mode 0: QKV fused (blockIdx.x<16 -> wq tile, <20 -> wk, else wv)
// mode 1: wo GEMM with X = g_attn
__global__ void __launch_bounds__(256) gemm16(const float* __restrict__ Xin,
                                              const float* __restrict__ W0,
                                              const float* __restrict__ W1,
                                              const float* __restrict__ W2,
                                              int mode)
{
    int t = blockIdx.x, ks = blockIdx.y;
    const float* X = Xin; const float* W; float* P; int N, ct;
    if (mode == 0) {
        if (t < 16)      { W = W0; P = g_Pq; N = 4096; ct = t; }
        else if (t < 20) { W = W1; P = g_Pk; N = 1024; ct = t - 16; }
        else             { W = W2; P = g_Pv; N = 1024; ct = t - 20; }
    } else {
        W = W0; P = g_Po; N = 4096; ct = t; X = g_attn;
    }

    __shared__ float xs[16][256];
    int kbase = ks * KSLICE;
    #pragma unroll
    for (int j = 0; j < 16; j++)
        xs[j][threadIdx.x] = X[j * 4096 + kbase + threadIdx.x];
    __syncthreads();

    int rg = threadIdx.x >> 6;        // 4 rows each
    int cg = threadIdx.x & 63;        // 4 cols each
    int col = ct * 256 + cg * 4;
    const float* Wp = W + (size_t)kbase * N + col;

    ull acc[4][2] = {};
    #pragma unroll 1
    for (int k = 0; k < KSLICE; k += 4) {
        ulonglong2 wv[4];
        #pragma unroll
        for (int kk = 0; kk < 4; kk++) { wv[kk] = *(const ulonglong2*)Wp; Wp += N; }
        #pragma unroll
        for (int i = 0; i < 4; i++) {
            float4 xq = *(const float4*)&xs[rg * 4 + i][k];
            ull xp;
            xp = pack2(xq.x, xq.x);
            acc[i][0] = ffma2(xp, wv[0].x, acc[i][0]);
            acc[i][1] = ffma2(xp, wv[0].y, acc[i][1]);
            xp = pack2(xq.y, xq.y);
            acc[i][0] = ffma2(xp, wv[1].x, acc[i][0]);
            acc[i][1] = ffma2(xp, wv[1].y, acc[i][1]);
            xp = pack2(xq.z, xq.z);
            acc[i][0] = ffma2(xp, wv[2].x, acc[i][0]);
            acc[i][1] = ffma2(xp, wv[2].y, acc[i][1]);
            xp = pack2(xq.w, xq.w);
            acc[i][0] = ffma2(xp, wv[3].x, acc[i][0]);
            acc[i][1] = ffma2(xp, wv[3].y, acc[i][1]);
        }
    }
    #pragma unroll
    for (int i = 0; i < 4; i++) {
        float* o = P + ((size_t)ks * 16 + rg * 4 + i) * N + col;
        *(ull*)(o)     = acc[i][0];
        *(ull*)(o + 2) = acc[i][1];
    }
}

// ---------------- combine K-split partials + l2norm ----------------
// blocks: [0,512) q heads, [512,640) k heads, [640,768) v heads; 128 threads = dims
__global__ void __launch_bounds__(128) norm_combine()
{
    __shared__ float red[4];
    int blk = blockIdx.x, d = threadIdx.x;
    float v = 0.f; float* outp; bool donorm;
    if (blk < 512) {
        int b = blk >> 5, h = blk & 31;
        const float* p = g_Pq + (size_t)b * 4096 + h * 128 + d;
        #pragma unroll
        for (int ks = 0; ks < 16; ks++) v += p[(size_t)ks * 16 * 4096];
        outp = g_q + (size_t)b * 4096 + h * 128 + d; donorm = true;
    } else if (blk < 640) {
        int idx = blk - 512; int b = idx >> 3, gg = idx & 7;
        const float* p = g_Pk + (size_t)b * 1024 + gg * 128 + d;
        #pragma unroll
        for (int ks = 0; ks < 16; ks++) v += p[(size_t)ks * 16 * 1024];
        outp = g_kn + (size_t)(b * 8 + gg) * 128 + d; donorm = true;
    } else {
        int idx = blk - 640; int b = idx >> 3, gg = idx & 7;
        const float* p = g_Pv + (size_t)b * 1024 + gg * 128 + d;
        #pragma unroll
        for (int ks = 0; ks < 16; ks++) v += p[(size_t)ks * 16 * 1024];
        outp = g_vn + (size_t)(b * 8 + gg) * 128 + d; donorm = false;
    }
    float s = v * v;
    #pragma unroll
    for (int m = 16; m >= 1; m >>= 1) s += __shfl_xor_sync(0xffffffffu, s, m);
    if ((d & 31) == 0) red[d >> 5] = s;
    __syncthreads();
    if (donorm) {
        float tot = red[0] + red[1] + red[2] + red[3];
        v *= rsqrtf(tot * (1.0f / 128.0f) + 1e-6f);
    }
    *outp = v;
}

// ---------------- fused single-pass attention ----------------
// grid (8 kv-heads, 16 batch), 256 threads. Each warp: 2 keys per iter
// (half-warp per key, 8 dims per lane). Fixed-offset softmax exp(s-16).
__global__ void __launch_bounds__(256) attention(const float* __restrict__ CK,
                                                 const float* __restrict__ CV)
{
    __shared__ float part[16][512];
    __shared__ float psum[16][4];

    int g = blockIdx.x, b = blockIdx.y;
    int tid = threadIdx.x, w = tid >> 5, lid = tid & 31;
    int half = lid >> 4, sub = lid & 15;

    const float* Kb = CK + (size_t)b * (SEQ * NKV * HD) + g * HD;
    const float* Vb = CV + (size_t)b * (SEQ * NKV * HD) + g * HD;
    const float* knrow = g_kn + (b * NKV + g) * HD + sub * 8;
    const float* vnrow = g_vn + (b * NKV + g) * HD + sub * 8;

    const float sc = 0.08838834764831845f;   // 1/sqrt(128)
    ull q2[4][4];
    #pragma unroll
    for (int r = 0; r < 4; r++) {
        const float* qp = g_q + (size_t)b * 4096 + (g * 4 + r) * 128 + sub * 8;
        float4 a = *(const float4*)qp;
        float4 c = *(const float4*)(qp + 4);
        q2[r][0] = pack2(a.x * sc, a.y * sc);
        q2[r][1] = pack2(a.z * sc, a.w * sc);
        q2[r][2] = pack2(c.x * sc, c.y * sc);
        q2[r][3] = pack2(c.z * sc, c.w * sc);
    }

    ull acc[4][4] = {};
    float ssum[4] = {0.f, 0.f, 0.f, 0.f};

    ulonglong2 kb[2][2], vb[2][2];
    auto ldkv = [&](int i, ulonglong2* kk, ulonglong2* vv) {
        int k = i * 16 + w * 2 + half;
        const float* kp = (k == SEQ - 1) ? knrow : (Kb + (size_t)k * (NKV * HD) + sub * 8);
        const float* vp = (k == SEQ - 1) ? vnrow : (Vb + (size_t)k * (NKV * HD) + sub * 8);
        kk[0] = *(const ulonglong2*)kp;
        kk[1] = *(const ulonglong2*)(kp + 4);
        vv[0] = *(const ulonglong2*)vp;
        vv[1] = *(const ulonglong2*)(vp + 4);
    };
    ldkv(0, kb[0], vb[0]);
    ldkv(1, kb[1], vb[1]);

    #pragma unroll 1
    for (int ii = 0; ii < 256; ii += 2) {
        #pragma unroll
        for (int u = 0; u < 2; u++) {
            int i = ii + u;
            ulonglong2 k0 = kb[u][0], k1 = kb[u][1];
            ulonglong2 v0 = vb[u][0], v1 = vb[u][1];
            if (i + 2 < 256) ldkv(i + 2, kb[u], vb[u]);   // depth-2 prefetch

            float p[4];
            #pragma unroll
            for (int r = 0; r < 4; r++) {
                ull t = fmul2(q2[r][0], k0.x);
                t = ffma2(q2[r][1], k0.y, t);
                t = ffma2(q2[r][2], k1.x, t);
                t = ffma2(q2[r][3], k1.y, t);
                float2 f = unpack2(t);
                p[r] = f.x + f.y;
            }
            #pragma unroll
            for (int m = 1; m <= 8; m <<= 1) {
                #pragma unroll
                for (int r = 0; r < 4; r++)
                    p[r] += __shfl_xor_sync(0xffffffffu, p[r], m);
            }
            #pragma unroll
            for (int r = 0; r < 4; r++) {
                float wgt = __expf(p[r] - 16.0f);   // fixed-offset softmax
                ssum[r] += wgt;
                ull wd = pack2(wgt, wgt);
                acc[r][0] = ffma2(wd, v0.x, acc[r][0]);
                acc[r][1] = ffma2(wd, v0.y, acc[r][1]);
                acc[r][2] = ffma2(wd, v1.x, acc[r][2]);
                acc[r][3] = ffma2(wd, v1.y, acc[r][3]);
            }
        }
    }

    // combine 16 half-warp partials
    int H = w * 2 + half;
    #pragma unroll
    for (int r = 0; r < 4; r++) {
        #pragma unroll
        for (int j = 0; j < 4; j++) {
            float2 f = unpack2(acc[r][j]);
            part[H][r * 128 + sub * 8 + j * 2]     = f.x;
            part[H][r * 128 + sub * 8 + j * 2 + 1] = f.y;
        }
        if (sub == 0) psum[H][r] = ssum[r];
    }
    __syncthreads();

    for (int idx = tid; idx < 512; idx += 256) {
        int r = idx >> 7;
        float tot = 0.f, ts = 0.f;
        #pragma unroll
        for (int Hh = 0; Hh < 16; Hh++) { tot += part[Hh][idx]; ts += psum[Hh][r]; }
        g_attn[(size_t)b * 4096 + g * 512 + idx] = tot / ts;
    }
}

// ---------------- final combine of wo K-split partials ----------------
__global__ void __launch_bounds__(256) combine_out(float* __restrict__ out)
{
    int e = blockIdx.x * 256 + threadIdx.x;   // 65536 elements
    float v = 0.f;
    #pragma unroll
    for (int ks = 0; ks < 16; ks++) v += g_Po[(size_t)ks * 65536 + e];
    out[e] = v;
}

// ---------------- launch ----------------
extern "C" void kernel_launch(void* const* d_in, const int* in_sizes, int n_in,
                              void* d_out, int out_size)
{
    const float* x  = (const float*)d_in[0];
    const float* wq = (const float*)d_in[1];
    const float* wk = (const float*)d_in[2];
    const float* wv = (const float*)d_in[3];
    const float* wo = (const float*)d_in[4];
    const float* ck = (const float*)d_in[5];
    const float* cv = (const float*)d_in[6];
    // d_in[7] freqs_complex: unused by reference; d_in[8] start_pos fixed at 4095

    gemm16<<<dim3(24, 16), 256>>>(x, wq, wk, wv, 0);
    norm_combine<<<768, 128>>>();
    attention<<<dim3(8, 16), 256>>>(ck, cv);
    gemm16<<<dim3(16, 16), 256>>>(x, wo, wo, wo, 1);
    combine_out<<<256, 256>>>((float*)d_out);
}

// round 2
// speedup vs baseline: 1.5290x; 1.5290x over previous
#include <cuda_runtime.h>
#include <cstdint>

typedef unsigned long long ull;

#define B_     16
#define D_     4096
#define NKV    8
#define HD     128
#define SEQ    4096
#define KSPLIT 32
#define KSLICE 128
#define ASPLIT 2

// ---------------- scratch ----------------
__device__ float g_q   [B_ * D_];
__device__ float g_kn  [B_ * NKV * HD];
__device__ float g_vn  [B_ * NKV * HD];
__device__ float g_attn[B_ * D_];
__device__ float g_Pq  [KSPLIT * B_ * D_];
__device__ float g_Pk  [KSPLIT * B_ * NKV * HD];
__device__ float g_Pv  [KSPLIT * B_ * NKV * HD];
__device__ float g_Po  [KSPLIT * B_ * D_];
__device__ float g_attp[ASPLIT * B_ * D_];           // unnormalized attention partials
__device__ float g_ssum[ASPLIT * B_ * NKV * 4];      // exp-sums per (split,b,g,r)

// ---------------- packed f32x2 helpers ----------------
__device__ __forceinline__ ull ffma2(ull a, ull b, ull c) {
    ull d; asm("fma.rn.f32x2 %0,%1,%2,%3;" : "=l"(d) : "l"(a), "l"(b), "l"(c)); return d;
}
__device__ __forceinline__ ull fmul2(ull a, ull b) {
    ull d; asm("mul.rn.f32x2 %0,%1,%2;" : "=l"(d) : "l"(a), "l"(b)); return d;
}
__device__ __forceinline__ ull pack2(float x, float y) {
    ull d; asm("mov.b64 %0,{%1,%2};" : "=l"(d) : "f"(x), "f"(y)); return d;
}
__device__ __forceinline__ float2 unpack2(ull a) {
    float2 r; asm("mov.b64 {%0,%1},%2;" : "=f"(r.x), "=f"(r.y) : "l"(a)); return r;
}

// ---------------- skinny GEMM: out[16,N] = X[16,4096] @ W[4096,N] ----------------
// K split across grid.y (32 slices of 128). Ping-pong prefetch of weight rows.
__global__ void __launch_bounds__(256, 3) gemm16(const float* __restrict__ Xin,
                                                 const float* __restrict__ W0,
                                                 const float* __restrict__ W1,
                                                 const float* __restrict__ W2,
                                                 int mode)
{
    int t = blockIdx.x, ks = blockIdx.y;
    const float* X = Xin; const float* W; float* P; int N, ct;
    if (mode == 0) {
        if (t < 16)      { W = W0; P = g_Pq; N = 4096; ct = t; }
        else if (t < 20) { W = W1; P = g_Pk; N = 1024; ct = t - 16; }
        else             { W = W2; P = g_Pv; N = 1024; ct = t - 20; }
    } else {
        W = W0; P = g_Po; N = 4096; ct = t; X = g_attn;
    }

    __shared__ float xs[16][KSLICE];
    int kbase = ks * KSLICE;
    for (int j = threadIdx.x; j < 16 * KSLICE; j += 256)
        xs[j >> 7][j & 127] = X[(j >> 7) * 4096 + kbase + (j & 127)];
    __syncthreads();

    int rg = threadIdx.x >> 6;        // 4 rows each
    int cg = threadIdx.x & 63;        // 4 cols each
    int col = ct * 256 + cg * 4;
    const float* Wp = W + (size_t)kbase * N + col;

    ull acc[4][2] = {};
    ulonglong2 wbuf[2][4];
    #pragma unroll
    for (int kk = 0; kk < 4; kk++) { wbuf[0][kk] = *(const ulonglong2*)Wp; Wp += N; }

    #pragma unroll 2
    for (int k = 0; k < KSLICE; k += 4) {
        int cur = (k >> 2) & 1, nxt = cur ^ 1;
        if (k + 4 < KSLICE) {
            #pragma unroll
            for (int kk = 0; kk < 4; kk++) { wbuf[nxt][kk] = *(const ulonglong2*)Wp; Wp += N; }
        }
        #pragma unroll
        for (int i = 0; i < 4; i++) {
            float4 xq = *(const float4*)&xs[rg * 4 + i][k];
            ull xp;
            xp = pack2(xq.x, xq.x);
            acc[i][0] = ffma2(xp, wbuf[cur][0].x, acc[i][0]);
            acc[i][1] = ffma2(xp, wbuf[cur][0].y, acc[i][1]);
            xp = pack2(xq.y, xq.y);
            acc[i][0] = ffma2(xp, wbuf[cur][1].x, acc[i][0]);
            acc[i][1] = ffma2(xp, wbuf[cur][1].y, acc[i][1]);
            xp = pack2(xq.z, xq.z);
            acc[i][0] = ffma2(xp, wbuf[cur][2].x, acc[i][0]);
            acc[i][1] = ffma2(xp, wbuf[cur][2].y, acc[i][1]);
            xp = pack2(xq.w, xq.w);
            acc[i][0] = ffma2(xp, wbuf[cur][3].x, acc[i][0]);
            acc[i][1] = ffma2(xp, wbuf[cur][3].y, acc[i][1]);
        }
    }
    #pragma unroll
    for (int i = 0; i < 4; i++) {
        float* o = P + ((size_t)ks * 16 + rg * 4 + i) * N + col;
        *(ull*)(o)     = acc[i][0];
        *(ull*)(o + 2) = acc[i][1];
    }
}

// ---------------- combine K-split partials + l2norm ----------------
__global__ void __launch_bounds__(128) norm_combine()
{
    __shared__ float red[4];
    int blk = blockIdx.x, d = threadIdx.x;
    float v = 0.f; float* outp; bool donorm;
    if (blk < 512) {
        int b = blk >> 5, h = blk & 31;
        const float* p = g_Pq + (size_t)b * 4096 + h * 128 + d;
        #pragma unroll
        for (int ks = 0; ks < KSPLIT; ks++) v += p[(size_t)ks * 16 * 4096];
        outp = g_q + (size_t)b * 4096 + h * 128 + d; donorm = true;
    } else if (blk < 640) {
        int idx = blk - 512; int b = idx >> 3, gg = idx & 7;
        const float* p = g_Pk + (size_t)b * 1024 + gg * 128 + d;
        #pragma unroll
        for (int ks = 0; ks < KSPLIT; ks++) v += p[(size_t)ks * 16 * 1024];
        outp = g_kn + (size_t)(b * 8 + gg) * 128 + d; donorm = true;
    } else {
        int idx = blk - 640; int b = idx >> 3, gg = idx & 7;
        const float* p = g_Pv + (size_t)b * 1024 + gg * 128 + d;
        #pragma unroll
        for (int ks = 0; ks < KSPLIT; ks++) v += p[(size_t)ks * 16 * 1024];
        outp = g_vn + (size_t)(b * 8 + gg) * 128 + d; donorm = false;
    }
    float s = v * v;
    #pragma unroll
    for (int m = 16; m >= 1; m >>= 1) s += __shfl_xor_sync(0xffffffffu, s, m);
    if ((d & 31) == 0) red[d >> 5] = s;
    __syncthreads();
    if (donorm) {
        float tot = red[0] + red[1] + red[2] + red[3];
        v *= rsqrtf(tot * (1.0f / 128.0f) + 1e-6f);
    }
    *outp = v;
}

// ---------------- fused attention (seq-split 2) ----------------
// grid (8 kv-heads, 16 batch, 2 seq-splits), 256 threads.
__global__ void __launch_bounds__(256, 2) attention(const float* __restrict__ CK,
                                                    const float* __restrict__ CV)
{
    __shared__ float part[16][512];
    __shared__ float psum[16][4];

    int g = blockIdx.x, b = blockIdx.y, sp = blockIdx.z;
    int tid = threadIdx.x, w = tid >> 5, lid = tid & 31;
    int half = lid >> 4, sub = lid & 15;
    int kb0 = sp * (SEQ / ASPLIT);

    const float* Kb = CK + (size_t)b * (SEQ * NKV * HD) + g * HD;
    const float* Vb = CV + (size_t)b * (SEQ * NKV * HD) + g * HD;
    const float* knrow = g_kn + (b * NKV + g) * HD + sub * 8;
    const float* vnrow = g_vn + (b * NKV + g) * HD + sub * 8;

    const float sc = 0.08838834764831845f;   // 1/sqrt(128)
    ull q2[4][4];
    #pragma unroll
    for (int r = 0; r < 4; r++) {
        const float* qp = g_q + (size_t)b * 4096 + (g * 4 + r) * 128 + sub * 8;
        float4 a = *(const float4*)qp;
        float4 c = *(const float4*)(qp + 4);
        q2[r][0] = pack2(a.x * sc, a.y * sc);
        q2[r][1] = pack2(a.z * sc, a.w * sc);
        q2[r][2] = pack2(c.x * sc, c.y * sc);
        q2[r][3] = pack2(c.z * sc, c.w * sc);
    }

    ull acc[4][4] = {};
    float ssum[4] = {0.f, 0.f, 0.f, 0.f};

    ulonglong2 kbuf[2][2], vbuf[2][2];
    auto ldkv = [&](int i, ulonglong2* kk, ulonglong2* vv) {
        int k = kb0 + i * 16 + w * 2 + half;
        const float* kp = (k == SEQ - 1) ? knrow : (Kb + (size_t)k * (NKV * HD) + sub * 8);
        const float* vp = (k == SEQ - 1) ? vnrow : (Vb + (size_t)k * (NKV * HD) + sub * 8);
        kk[0] = *(const ulonglong2*)kp;
        kk[1] = *(const ulonglong2*)(kp + 4);
        vv[0] = *(const ulonglong2*)vp;
        vv[1] = *(const ulonglong2*)(vp + 4);
    };
    ldkv(0, kbuf[0], vbuf[0]);
    ldkv(1, kbuf[1], vbuf[1]);

    const int NI = (SEQ / ASPLIT) / 16;   // 128
    #pragma unroll 1
    for (int ii = 0; ii < NI; ii += 2) {
        #pragma unroll
        for (int u = 0; u < 2; u++) {
            int i = ii + u;
            ulonglong2 k0 = kbuf[u][0], k1 = kbuf[u][1];
            ulonglong2 v0 = vbuf[u][0], v1 = vbuf[u][1];
            if (i + 2 < NI) ldkv(i + 2, kbuf[u], vbuf[u]);

            float p[4];
            #pragma unroll
            for (int r = 0; r < 4; r++) {
                ull t = fmul2(q2[r][0], k0.x);
                t = ffma2(q2[r][1], k0.y, t);
                t = ffma2(q2[r][2], k1.x, t);
                t = ffma2(q2[r][3], k1.y, t);
                float2 f = unpack2(t);
                p[r] = f.x + f.y;
            }
            #pragma unroll
            for (int m = 1; m <= 8; m <<= 1) {
                #pragma unroll
                for (int r = 0; r < 4; r++)
                    p[r] += __shfl_xor_sync(0xffffffffu, p[r], m);
            }
            #pragma unroll
            for (int r = 0; r < 4; r++) {
                float wgt = __expf(p[r] - 16.0f);
                ssum[r] += wgt;
                ull wd = pack2(wgt, wgt);
                acc[r][0] = ffma2(wd, v0.x, acc[r][0]);
                acc[r][1] = ffma2(wd, v0.y, acc[r][1]);
                acc[r][2] = ffma2(wd, v1.x, acc[r][2]);
                acc[r][3] = ffma2(wd, v1.y, acc[r][3]);
            }
        }
    }

    int H = w * 2 + half;
    #pragma unroll
    for (int r = 0; r < 4; r++) {
        #pragma unroll
        for (int j = 0; j < 4; j++) {
            float2 f = unpack2(acc[r][j]);
            part[H][r * 128 + sub * 8 + j * 2]     = f.x;
            part[H][r * 128 + sub * 8 + j * 2 + 1] = f.y;
        }
        if (sub == 0) psum[H][r] = ssum[r];
    }
    __syncthreads();

    for (int idx = tid; idx < 512; idx += 256) {
        int r = idx >> 7;
        float tot = 0.f, ts = 0.f;
        #pragma unroll
        for (int Hh = 0; Hh < 16; Hh++) { tot += part[Hh][idx]; ts += psum[Hh][r]; }
        g_attp[(size_t)(sp * 16 + b) * 4096 + g * 512 + idx] = tot;
        if ((idx & 127) == 0)
            g_ssum[(size_t)sp * (16 * 8 * 4) + (b * 8 + g) * 4 + r] = ts;
    }
}

// ---------------- combine attention seq-splits ----------------
__global__ void __launch_bounds__(256) att_combine()
{
    int e = blockIdx.x * 256 + threadIdx.x;  // 65536: b*4096 + g*512 + r*128 + d
    int b = e >> 12, rem = e & 4095, gg = rem >> 9, r = (rem >> 7) & 3;
    float t = 0.f, s = 0.f;
    #pragma unroll
    for (int sp = 0; sp < ASPLIT; sp++) {
        t += g_attp[(size_t)(sp * 16 + b) * 4096 + rem];
        s += g_ssum[(size_t)sp * (16 * 8 * 4) + (b * 8 + gg) * 4 + r];
    }
    g_attn[e] = t / s;
}

// ---------------- final combine of wo K-split partials ----------------
__global__ void __launch_bounds__(256) combine_out(float* __restrict__ out)
{
    int e = blockIdx.x * 256 + threadIdx.x;
    float v = 0.f;
    #pragma unroll
    for (int ks = 0; ks < KSPLIT; ks++) v += g_Po[(size_t)ks * 65536 + e];
    out[e] = v;
}

// ---------------- launch ----------------
extern "C" void kernel_launch(void* const* d_in, const int* in_sizes, int n_in,
                              void* d_out, int out_size)
{
    const float* x  = (const float*)d_in[0];
    const float* wq = (const float*)d_in[1];
    const float* wk = (const float*)d_in[2];
    const float* wv = (const float*)d_in[3];
    const float* wo = (const float*)d_in[4];
    const float* ck = (const float*)d_in[5];
    const float* cv = (const float*)d_in[6];

    gemm16<<<dim3(24, KSPLIT), 256>>>(x, wq, wk, wv, 0);
    norm_combine<<<768, 128>>>();
    attention<<<dim3(8, 16, ASPLIT), 256>>>(ck, cv);
    att_combine<<<256, 256>>>();
    gemm16<<<dim3(16, KSPLIT), 256>>>(x, wo, wo, wo, 1);
    combine_out<<<256, 256>>>((float*)d_out);
}

// round 3
// speedup vs baseline: 1.6255x; 1.0631x over previous
#include <cuda_runtime.h>
#include <cstdint>

typedef unsigned long long ull;

#define B_     16
#define D_     4096
#define NKV    8
#define HD     128
#define SEQ    4096
#define KSPLIT 32
#define KSLICE 128
#define STAGES 4

// ---------------- scratch ----------------
__device__ float g_q   [B_ * D_];
__device__ float g_kn  [B_ * NKV * HD];
__device__ float g_vn  [B_ * NKV * HD];
__device__ float g_attn[B_ * D_];
__device__ float g_Pq  [KSPLIT * B_ * D_];
__device__ float g_Pk  [KSPLIT * B_ * NKV * HD];
__device__ float g_Pv  [KSPLIT * B_ * NKV * HD];
__device__ float g_Po  [KSPLIT * B_ * D_];

// ---------------- packed f32x2 helpers ----------------
__device__ __forceinline__ ull ffma2(ull a, ull b, ull c) {
    ull d; asm("fma.rn.f32x2 %0,%1,%2,%3;" : "=l"(d) : "l"(a), "l"(b), "l"(c)); return d;
}
__device__ __forceinline__ ull fmul2(ull a, ull b) {
    ull d; asm("mul.rn.f32x2 %0,%1,%2;" : "=l"(d) : "l"(a), "l"(b)); return d;
}
__device__ __forceinline__ ull fadd2(ull a, ull b) {
    ull d; asm("add.rn.f32x2 %0,%1,%2;" : "=l"(d) : "l"(a), "l"(b)); return d;
}
__device__ __forceinline__ ull pack2(float x, float y) {
    ull d; asm("mov.b64 %0,{%1,%2};" : "=l"(d) : "f"(x), "f"(y)); return d;
}
__device__ __forceinline__ float2 unpack2(ull a) {
    float2 r; asm("mov.b64 {%0,%1},%2;" : "=f"(r.x), "=f"(r.y) : "l"(a)); return r;
}
__device__ __forceinline__ ull redshfl2(ull v, int m) {
    float2 f = unpack2(v);
    float x = __shfl_xor_sync(0xffffffffu, f.x, m);
    float y = __shfl_xor_sync(0xffffffffu, f.y, m);
    return fadd2(v, pack2(x, y));
}

#define CP16(dst, src) asm volatile("cp.async.cg.shared.global [%0],[%1],16;\n" :: "r"(dst), "l"(src) : "memory")
#define CPCOMMIT()     asm volatile("cp.async.commit_group;\n" ::: "memory")
#define CPWAIT3()      asm volatile("cp.async.wait_group 3;\n" ::: "memory")

// ---------------- skinny GEMM: out[16,N] = X[16,4096] @ W[4096,N] ----------------
__global__ void __launch_bounds__(256, 3) gemm16(const float* __restrict__ Xin,
                                                 const float* __restrict__ W0,
                                                 const float* __restrict__ W1,
                                                 const float* __restrict__ W2,
                                                 int mode)
{
    int t = blockIdx.x, ks = blockIdx.y;
    const float* X = Xin; const float* W; float* P; int N, ct;
    if (mode == 0) {
        if (t < 16)      { W = W0; P = g_Pq; N = 4096; ct = t; }
        else if (t < 20) { W = W1; P = g_Pk; N = 1024; ct = t - 16; }
        else             { W = W2; P = g_Pv; N = 1024; ct = t - 20; }
    } else {
        W = W0; P = g_Po; N = 4096; ct = t; X = g_attn;
    }

    __shared__ float xs[16][KSLICE];
    int kbase = ks * KSLICE;
    for (int j = threadIdx.x; j < 16 * KSLICE; j += 256)
        xs[j >> 7][j & 127] = X[(j >> 7) * 4096 + kbase + (j & 127)];
    __syncthreads();

    int rg = threadIdx.x >> 6;
    int cg = threadIdx.x & 63;
    int col = ct * 256 + cg * 4;
    const float* Wp = W + (size_t)kbase * N + col;

    ull acc[4][2] = {};
    ulonglong2 wbuf[2][4];
    #pragma unroll
    for (int kk = 0; kk < 4; kk++) { wbuf[0][kk] = *(const ulonglong2*)Wp; Wp += N; }

    #pragma unroll 2
    for (int k = 0; k < KSLICE; k += 4) {
        int cur = (k >> 2) & 1, nxt = cur ^ 1;
        if (k + 4 < KSLICE) {
            #pragma unroll
            for (int kk = 0; kk < 4; kk++) { wbuf[nxt][kk] = *(const ulonglong2*)Wp; Wp += N; }
        }
        #pragma unroll
        for (int i = 0; i < 4; i++) {
            float4 xq = *(const float4*)&xs[rg * 4 + i][k];
            ull xp;
            xp = pack2(xq.x, xq.x);
            acc[i][0] = ffma2(xp, wbuf[cur][0].x, acc[i][0]);
            acc[i][1] = ffma2(xp, wbuf[cur][0].y, acc[i][1]);
            xp = pack2(xq.y, xq.y);
            acc[i][0] = ffma2(xp, wbuf[cur][1].x, acc[i][0]);
            acc[i][1] = ffma2(xp, wbuf[cur][1].y, acc[i][1]);
            xp = pack2(xq.z, xq.z);
            acc[i][0] = ffma2(xp, wbuf[cur][2].x, acc[i][0]);
            acc[i][1] = ffma2(xp, wbuf[cur][2].y, acc[i][1]);
            xp = pack2(xq.w, xq.w);
            acc[i][0] = ffma2(xp, wbuf[cur][3].x, acc[i][0]);
            acc[i][1] = ffma2(xp, wbuf[cur][3].y, acc[i][1]);
        }
    }
    #pragma unroll
    for (int i = 0; i < 4; i++) {
        float* o = P + ((size_t)ks * 16 + rg * 4 + i) * N + col;
        *(ull*)(o)     = acc[i][0];
        *(ull*)(o + 2) = acc[i][1];
    }
}

// ---------------- combine K-split partials + l2norm ----------------
__global__ void __launch_bounds__(128) norm_combine()
{
    __shared__ float red[4];
    int blk = blockIdx.x, d = threadIdx.x;
    float v = 0.f; float* outp; bool donorm;
    if (blk < 512) {
        int b = blk >> 5, h = blk & 31;
        const float* p = g_Pq + (size_t)b * 4096 + h * 128 + d;
        #pragma unroll
        for (int ks = 0; ks < KSPLIT; ks++) v += p[(size_t)ks * 16 * 4096];
        outp = g_q + (size_t)b * 4096 + h * 128 + d; donorm = true;
    } else if (blk < 640) {
        int idx = blk - 512; int b = idx >> 3, gg = idx & 7;
        const float* p = g_Pk + (size_t)b * 1024 + gg * 128 + d;
        #pragma unroll
        for (int ks = 0; ks < KSPLIT; ks++) v += p[(size_t)ks * 16 * 1024];
        outp = g_kn + (size_t)(b * 8 + gg) * 128 + d; donorm = true;
    } else {
        int idx = blk - 640; int b = idx >> 3, gg = idx & 7;
        const float* p = g_Pv + (size_t)b * 1024 + gg * 128 + d;
        #pragma unroll
        for (int ks = 0; ks < KSPLIT; ks++) v += p[(size_t)ks * 16 * 1024];
        outp = g_vn + (size_t)(b * 8 + gg) * 128 + d; donorm = false;
    }
    float s = v * v;
    #pragma unroll
    for (int m = 16; m >= 1; m >>= 1) s += __shfl_xor_sync(0xffffffffu, s, m);
    if ((d & 31) == 0) red[d >> 5] = s;
    __syncthreads();
    if (donorm) {
        float tot = red[0] + red[1] + red[2] + red[3];
        v *= rsqrtf(tot * (1.0f / 128.0f) + 1e-6f);
    }
    *outp = v;
}

// ---------------- attention: cp.async 4-stage warp-private pipeline ----------------
// grid (8, 16), 512 threads (16 warps). Each warp owns key slots H=2w,2w+1;
// each lane cp.asyncs exactly the 32B of K and 32B of V it later reads.
__global__ void __launch_bounds__(512, 1) attention(const float* __restrict__ CK,
                                                    const float* __restrict__ CV)
{
    extern __shared__ float sm[];
    float* ksm  = sm;                        // [STAGES][32][128]
    float* vsm  = sm + STAGES * 32 * 128;    // [STAGES][32][128]
    float* part = vsm + STAGES * 32 * 128;   // [32][512]
    float* psum = part + 32 * 512;           // [32][4]

    int g = blockIdx.x, b = blockIdx.y;
    int tid = threadIdx.x, w = tid >> 5, lid = tid & 31;
    int half = lid >> 4, sub = lid & 15;
    int H = w * 2 + half;                    // key slot 0..31

    const float* Kb = CK + (size_t)b * (SEQ * NKV * HD) + g * HD + sub * 8;
    const float* Vb = CV + (size_t)b * (SEQ * NKV * HD) + g * HD + sub * 8;
    const float* knrow = g_kn + (b * NKV + g) * HD + sub * 8;
    const float* vnrow = g_vn + (b * NKV + g) * HD + sub * 8;

    uint32_t kdst0 = (uint32_t)__cvta_generic_to_shared(ksm + (size_t)H * 128 + sub * 8);
    uint32_t vdst0 = (uint32_t)__cvta_generic_to_shared(vsm + (size_t)H * 128 + sub * 8);

    const float sc = 0.08838834764831845f;   // 1/sqrt(128)
    ull q2[4][4];
    #pragma unroll
    for (int r = 0; r < 4; r++) {
        const float* qp = g_q + (size_t)b * 4096 + (g * 4 + r) * 128 + sub * 8;
        float4 a = *(const float4*)qp;
        float4 c = *(const float4*)(qp + 4);
        q2[r][0] = pack2(a.x * sc, a.y * sc);
        q2[r][1] = pack2(a.z * sc, a.w * sc);
        q2[r][2] = pack2(c.x * sc, c.y * sc);
        q2[r][3] = pack2(c.z * sc, c.w * sc);
    }

    auto copy_stage = [&](int st, int step) {
        int k = step * 32 + H;
        const float* kp = (k == SEQ - 1) ? knrow : (Kb + (size_t)k * (NKV * HD));
        const float* vp = (k == SEQ - 1) ? vnrow : (Vb + (size_t)k * (NKV * HD));
        uint32_t kd = kdst0 + st * (32 * 128 * 4);
        uint32_t vd = vdst0 + st * (32 * 128 * 4);
        CP16(kd, kp);       CP16(kd + 16, kp + 4);
        CP16(vd, vp);       CP16(vd + 16, vp + 4);
    };

    #pragma unroll
    for (int s = 0; s < STAGES; s++) { copy_stage(s, s); CPCOMMIT(); }

    ull acc[4][4] = {};
    float ssum[4] = {0.f, 0.f, 0.f, 0.f};

    #pragma unroll 1
    for (int i = 0; i < SEQ / 32; i++) {
        CPWAIT3();
        int st = i & (STAGES - 1);
        const float* kr = ksm + (size_t)(st * 32 + H) * 128 + sub * 8;
        const float* vr = vsm + (size_t)(st * 32 + H) * 128 + sub * 8;
        ulonglong2 k0 = *(const ulonglong2*)kr;
        ulonglong2 k1 = *(const ulonglong2*)(kr + 4);
        ulonglong2 v0 = *(const ulonglong2*)vr;
        ulonglong2 v1 = *(const ulonglong2*)(vr + 4);

        if (i + STAGES < SEQ / 32) copy_stage(st, i + STAGES);
        CPCOMMIT();

        float p[4];
        #pragma unroll
        for (int r = 0; r < 4; r++) {
            ull t = fmul2(q2[r][0], k0.x);
            t = ffma2(q2[r][1], k0.y, t);
            t = ffma2(q2[r][2], k1.x, t);
            t = ffma2(q2[r][3], k1.y, t);
            float2 f = unpack2(t);
            p[r] = f.x + f.y;
        }
        // packed butterfly over the 16-lane half-warp
        ull p01 = pack2(p[0], p[1]), p23 = pack2(p[2], p[3]);
        #pragma unroll
        for (int m = 1; m <= 8; m <<= 1) {
            p01 = redshfl2(p01, m);
            p23 = redshfl2(p23, m);
        }
        float2 fa = unpack2(p01), fc = unpack2(p23);
        float w0 = __expf(fa.x - 16.0f);
        float w1 = __expf(fa.y - 16.0f);
        float w2 = __expf(fc.x - 16.0f);
        float w3 = __expf(fc.y - 16.0f);
        ssum[0] += w0; ssum[1] += w1; ssum[2] += w2; ssum[3] += w3;
        ull wd;
        wd = pack2(w0, w0);
        acc[0][0] = ffma2(wd, v0.x, acc[0][0]);
        acc[0][1] = ffma2(wd, v0.y, acc[0][1]);
        acc[0][2] = ffma2(wd, v1.x, acc[0][2]);
        acc[0][3] = ffma2(wd, v1.y, acc[0][3]);
        wd = pack2(w1, w1);
        acc[1][0] = ffma2(wd, v0.x, acc[1][0]);
        acc[1][1] = ffma2(wd, v0.y, acc[1][1]);
        acc[1][2] = ffma2(wd, v1.x, acc[1][2]);
        acc[1][3] = ffma2(wd, v1.y, acc[1][3]);
        wd = pack2(w2, w2);
        acc[2][0] = ffma2(wd, v0.x, acc[2][0]);
        acc[2][1] = ffma2(wd, v0.y, acc[2][1]);
        acc[2][2] = ffma2(wd, v1.x, acc[2][2]);
        acc[2][3] = ffma2(wd, v1.y, acc[2][3]);
        wd = pack2(w3, w3);
        acc[3][0] = ffma2(wd, v0.x, acc[3][0]);
        acc[3][1] = ffma2(wd, v0.y, acc[3][1]);
        acc[3][2] = ffma2(wd, v1.x, acc[3][2]);
        acc[3][3] = ffma2(wd, v1.y, acc[3][3]);
    }

    // dump partials
    #pragma unroll
    for (int r = 0; r < 4; r++) {
        #pragma unroll
        for (int j = 0; j < 4; j++)
            *(ull*)&part[(size_t)H * 512 + r * 128 + sub * 8 + j * 2] = acc[r][j];
        if (sub == 0) psum[H * 4 + r] = ssum[r];
    }
    __syncthreads();

    // final reduce: thread tid handles one of 512 outputs
    int r = tid >> 7;
    float tot = 0.f, ts = 0.f;
    #pragma unroll
    for (int h2 = 0; h2 < 32; h2++) {
        tot += part[(size_t)h2 * 512 + tid];
        ts  += psum[h2 * 4 + r];
    }
    g_attn[(size_t)b * 4096 + g * 512 + tid] = tot / ts;
}

// ---------------- final combine of wo K-split partials ----------------
__global__ void __launch_bounds__(256) combine_out(float* __restrict__ out)
{
    int e = blockIdx.x * 256 + threadIdx.x;
    float v = 0.f;
    #pragma unroll
    for (int ks = 0; ks < KSPLIT; ks++) v += g_Po[(size_t)ks * 65536 + e];
    out[e] = v;
}

// ---------------- launch ----------------
extern "C" void kernel_launch(void* const* d_in, const int* in_sizes, int n_in,
                              void* d_out, int out_size)
{
    const float* x  = (const float*)d_in[0];
    const float* wq = (const float*)d_in[1];
    const float* wk = (const float*)d_in[2];
    const float* wv = (const float*)d_in[3];
    const float* wo = (const float*)d_in[4];
    const float* ck = (const float*)d_in[5];
    const float* cv = (const float*)d_in[6];

    const int attn_smem = (STAGES * 32 * 128 * 2 + 32 * 512 + 128) * 4;  // 197120 B
    static int smem_set = 0;
    if (!smem_set) {
        cudaFuncSetAttribute(attention, cudaFuncAttributeMaxDynamicSharedMemorySize, attn_smem);
        smem_set = 1;
    }

    gemm16<<<dim3(24, KSPLIT), 256>>>(x, wq, wk, wv, 0);
    norm_combine<<<768, 128>>>();
    attention<<<dim3(8, 16), 512, attn_smem>>>(ck, cv);
    gemm16<<<dim3(16, KSPLIT), 256>>>(x, wo, wo, wo, 1);
    combine_out<<<256, 256>>>((float*)d_out);
}